// round 3
// baseline (speedup 1.0000x reference)
#include <cuda_runtime.h>
#include <cuda_bf16.h>
#include <math.h>

// Problem constants
#define PP   256          // para_code dim
#define FF   20           // feature channels == depth
#define HH   18
#define WW   18
#define HW   (HH*WW)      // 324
#define VOL  (FF*HH*WW)   // 6480
#define MAXB 4096
#define ROWS 32           // batch rows per block in the param kernel
#define PI_F 3.14159f

// Padded volume: 21x21 per layer, 20 layers
#define PW   21
#define PLAY (PW*PW)      // 441
#define PVOL (FF*PLAY)    // 8820

// Raw per-(b,f) params: c, s, scale, tx, ty  (stride 5)
__device__ float g_params[MAXB * FF * 5];

// ---------------------------------------------------------------------------
// f32x2 helpers (FFMA2 — only reachable via PTX)
// ---------------------------------------------------------------------------
typedef unsigned long long u64;

__device__ __forceinline__ u64 pack2(float lo, float hi) {
    u64 d;
    asm("mov.b64 %0, {%1, %2};" : "=l"(d)
        : "r"(__float_as_uint(lo)), "r"(__float_as_uint(hi)));
    return d;
}
__device__ __forceinline__ u64 fma2(u64 a, u64 b, u64 c) {
    u64 d;
    asm("fma.rn.f32x2 %0, %1, %2, %3;" : "=l"(d) : "l"(a), "l"(b), "l"(c));
    return d;
}
__device__ __forceinline__ float2 unpack2(u64 v) {
    unsigned lo, hi;
    asm("mov.b64 {%0, %1}, %2;" : "=r"(lo), "=r"(hi) : "l"(v));
    float2 f; f.x = __uint_as_float(lo); f.y = __uint_as_float(hi);
    return f;
}

// Dynamic smem layout for the params kernel (bytes):
//   pcs2 : PP * 34 u64  (dup'd pc, [k][r] stride 34)   = 69632
//   hsm  : PP * 33 f32  ([hidden][row] stride 33)      = 33792
//   wsm  : PP * 80 f32  (Ws|Wr|Wt concatenated)        = 81920
#define PCS2_U64_STRIDE 34
#define HS_STRIDE       33
#define OFF_HS   (PP * PCS2_U64_STRIDE * 8)            // 69632
#define OFF_W    (OFF_HS + PP * HS_STRIDE * 4)         // 103424
#define SMEM_PAR (OFF_W + PP * 80 * 4)                 // 185344

// ---------------------------------------------------------------------------
// Kernel 1: h = relu(pc @ W1 + b1); scale/angle/trans heads -> g_params.
// 32 rows/block, 256 threads. Phase 1: 8x4 register tile with FFMA2.
// ---------------------------------------------------------------------------
__global__ __launch_bounds__(256) void adaat_params_kernel(
    const float* __restrict__ pc, int B,
    const float* __restrict__ W1, const float* __restrict__ b1,
    const float* __restrict__ Ws, const float* __restrict__ bs,
    const float* __restrict__ Wr, const float* __restrict__ br,
    const float* __restrict__ Wt, const float* __restrict__ bt)
{
    extern __shared__ char smem_raw[];
    float2* pcs2 = (float2*)smem_raw;                 // [k][r] dup'd
    float*  hsm  = (float*)(smem_raw + OFF_HS);       // [hidden][row]
    float*  wsm  = (float*)(smem_raw + OFF_W);        // [k][80]
    float4* wsm4 = (float4*)wsm;                      // [k][20] float4 groups

    const int b0  = blockIdx.x * ROWS;
    const int tid = threadIdx.x;

    // ---- stage pc (transposed + duplicated) ----
    for (int i = tid; i < ROWS * PP; i += 256) {
        int r = i >> 8;            // 0..31
        int k = i & (PP - 1);
        float v = (b0 + r < B) ? pc[(size_t)(b0 + r) * PP + k] : 0.f;
        pcs2[k * PCS2_U64_STRIDE + r] = make_float2(v, v);
    }
    // ---- stage head weights: wsm4[k*20 + 0..4]=Ws, 5..9=Wr, 10..19=Wt ----
    {
        const float4* Ws4 = (const float4*)Ws;
        const float4* Wr4 = (const float4*)Wr;
        const float4* Wt4 = (const float4*)Wt;
        for (int idx = tid; idx < 5120; idx += 256) {
            if (idx < 1280) {
                int k = idx / 5, c = idx % 5;
                wsm4[k * 20 + c] = Ws4[idx];
            } else if (idx < 2560) {
                int j = idx - 1280;
                int k = j / 5, c = j % 5;
                wsm4[k * 20 + 5 + c] = Wr4[j];
            } else {
                int j = idx - 2560;
                int k = j / 10, c = j % 10;
                wsm4[k * 20 + 10 + c] = Wt4[j];
            }
        }
    }
    __syncthreads();

    // ---- phase 1: (32 x 256) = pc_rows x hidden, FFMA2 ----
    const int tr = tid >> 6;       // 0..3 -> rows tr*8 .. +7
    const int tc = tid & 63;       // 0..63 -> cols tc*4 .. +3 (2 f32x2 pairs)

    u64 acc[8][2];
    {
        float4 bj = *(const float4*)(b1 + tc * 4);
        u64 blo = pack2(bj.x, bj.y), bhi = pack2(bj.z, bj.w);
        #pragma unroll
        for (int r = 0; r < 8; r++) { acc[r][0] = blo; acc[r][1] = bhi; }
    }
    const float2* arow = pcs2 + tr * 8;
    #pragma unroll 4
    for (int k = 0; k < PP; k++) {
        const ulonglong2* ap = (const ulonglong2*)(arow + (size_t)k * PCS2_U64_STRIDE);
        ulonglong2 q0 = ap[0], q1 = ap[1], q2 = ap[2], q3 = ap[3];
        u64 ad[8] = {q0.x, q0.y, q1.x, q1.y, q2.x, q2.y, q3.x, q3.y};
        float4 w = *(const float4*)(W1 + (size_t)k * PP + tc * 4);
        u64 wlo = pack2(w.x, w.y), whi = pack2(w.z, w.w);
        #pragma unroll
        for (int r = 0; r < 8; r++) {
            acc[r][0] = fma2(ad[r], wlo, acc[r][0]);
            acc[r][1] = fma2(ad[r], whi, acc[r][1]);
        }
    }
    // ReLU + store transposed: hsm[hidden][row]
    #pragma unroll
    for (int r = 0; r < 8; r++) {
        #pragma unroll
        for (int cj = 0; cj < 2; cj++) {
            float2 v = unpack2(acc[r][cj]);
            int col = tc * 4 + cj * 2;
            int row = tr * 8 + r;
            hsm[(col + 0) * HS_STRIDE + row] = fmaxf(v.x, 0.f);
            hsm[(col + 1) * HS_STRIDE + row] = fmaxf(v.y, 0.f);
        }
    }
    __syncthreads();

    // ---- phase 2: 32 rows x 20 float4 col-groups = 640 tasks ----
    for (int t = tid; t < ROWS * 20; t += 256) {
        int r  = t / 20;
        int cg = t - r * 20;

        float4 bb;
        if (cg < 5)       bb = ((const float4*)bs)[cg];
        else if (cg < 10) bb = ((const float4*)br)[cg - 5];
        else              bb = ((const float4*)bt)[cg - 10];
        float o0 = bb.x, o1 = bb.y, o2 = bb.z, o3 = bb.w;

        const float* hp = hsm + r;
        #pragma unroll 4
        for (int k = 0; k < PP; k++) {
            float  h = hp[k * HS_STRIDE];
            float4 w = wsm4[k * 20 + cg];
            o0 = fmaf(h, w.x, o0);
            o1 = fmaf(h, w.y, o1);
            o2 = fmaf(h, w.z, o2);
            o3 = fmaf(h, w.w, o3);
        }

        if (b0 + r >= B) continue;
        float* pb = g_params + (size_t)(b0 + r) * (FF * 5);
        float o4[4] = {o0, o1, o2, o3};
        if (cg < 5) {
            #pragma unroll
            for (int ci = 0; ci < 4; ci++)
                pb[(cg * 4 + ci) * 5 + 2] = 2.f / (1.f + expf(-o4[ci]));
        } else if (cg < 10) {
            #pragma unroll
            for (int ci = 0; ci < 4; ci++) {
                float ang = tanhf(o4[ci]) * PI_F;
                int f = (cg - 5) * 4 + ci;
                pb[f * 5 + 0] = cosf(ang);
                pb[f * 5 + 1] = sinf(ang);
            }
        } else {
            #pragma unroll
            for (int ci = 0; ci < 4; ci++) {
                int o = (cg - 10) * 4 + ci;
                pb[(o >> 1) * 5 + 3 + (o & 1)] = tanhf(o4[ci]);
            }
        }
    }
}

// ---------------------------------------------------------------------------
// Kernel 2: trilinear sample. One CTA per batch element, block (18,18).
// Zero-padded 21x21 layers in SMEM; coords clamped to [-1,18] so all taps
// are in-bounds and validity masking comes for free from the zero border.
// ---------------------------------------------------------------------------
__global__ __launch_bounds__(324) void adaat_sample_kernel(
    const float* __restrict__ fm, float* __restrict__ out)
{
    const int b  = blockIdx.x;
    const int tx = threadIdx.x;       // 0..17
    const int ty = threadIdx.y;       // 0..17
    const int tid = ty * WW + tx;     // 0..323

    __shared__ float  vols[PVOL];     // padded volume
    __shared__ float4 cfA[FF];        // axx, axy, cx, zw0
    __shared__ float4 cfB[FF];        // ayx, ayy, cy, zw1
    __shared__ int2   zb[FF];         // z0*441, z1*441

    // zero the padded volume
    {
        float4* pv4 = (float4*)vols;
        #pragma unroll
        for (int i = tid; i < PVOL / 4; i += HW)
            pv4[i] = make_float4(0.f, 0.f, 0.f, 0.f);
    }
    __syncthreads();

    // fill interior: vols[z][y+1][x+1] = fm[b][z][y][x]
    {
        const float* src = fm + (size_t)b * VOL + tid;
        float* dst = vols + ty * PW + tx + (PW + 1);
        #pragma unroll
        for (int z = 0; z < FF; z++)
            dst[z * PLAY] = src[z * HW];
    }

    // per-channel coefficients
    if (tid < FF) {
        const float* p = g_params + (size_t)(b * FF + tid) * 5;
        float c = p[0], s = p[1], sc = p[2], txp = p[3], typ = p[4];
        float kk = sc * (2.f / (WW - 1)) * (WW * 0.5f);   // sc*18/17
        float axx = c * kk,  axy = -s * kk;
        float ayx = s * kk,  ayy =  c * kk;
        float cx = (WW * 0.5f) * (txp - sc * c + sc * s) + (WW - 1) * 0.5f;
        float cy = (HH * 0.5f) * (typ - sc * s - sc * c) + (HH - 1) * 0.5f;

        // z taps: iz = 20f/19 - 0.5
        float iz  = (float)tid * ((float)FF / (FF - 1)) - 0.5f;
        float z0f = floorf(iz);
        float wz  = iz - z0f;
        int   z0  = (int)z0f, z1 = z0 + 1;
        float w0  = (z0 >= 0 && z0 < FF) ? (1.f - wz) : 0.f;
        float w1  = (z1 >= 0 && z1 < FF) ? wz         : 0.f;
        int   zb0 = min(max(z0, 0), FF - 1) * PLAY;
        int   zb1 = min(max(z1, 0), FF - 1) * PLAY;

        cfA[tid] = make_float4(axx, axy, cx, w0);
        cfB[tid] = make_float4(ayx, ayy, cy, w1);
        zb[tid]  = make_int2(zb0, zb1);
    }
    __syncthreads();

    const float fx = (float)tx, fy = (float)ty;
    float* outb = out + (size_t)b * VOL + tid;

    #pragma unroll 4
    for (int f = 0; f < FF; f++) {
        float4 A  = cfA[f];
        float4 Bv = cfB[f];
        int2   zo = zb[f];

        float ix = fmaf(A.x,  fx, fmaf(A.y,  fy, A.z));
        float iy = fmaf(Bv.x, fx, fmaf(Bv.y, fy, Bv.z));
        ix = fminf(fmaxf(ix, -1.f), (float)WW);
        iy = fminf(fmaxf(iy, -1.f), (float)HH);

        int   x0 = __float2int_rd(ix);
        int   y0 = __float2int_rd(iy);
        float wx = ix - (float)x0;
        float wy = iy - (float)y0;
        float wx0 = 1.f - wx, wy0 = 1.f - wy;

        float b00 = wx0 * wy0, b10 = wx * wy0;
        float b01 = wx0 * wy,  b11 = wx * wy;

        int base = y0 * PW + x0 + (PW + 1);
        const float* p0 = vols + zo.x + base;
        const float* p1 = vols + zo.y + base;

        float s0 = b00 * p0[0] + b10 * p0[1] + b01 * p0[PW] + b11 * p0[PW + 1];
        float s1 = b00 * p1[0] + b10 * p1[1] + b01 * p1[PW] + b11 * p1[PW + 1];

        outb[f * HW] = fmaf(A.w, s0, Bv.w * s1);
    }
}

// ---------------------------------------------------------------------------
// Launch
// ---------------------------------------------------------------------------
extern "C" void kernel_launch(void* const* d_in, const int* in_sizes, int n_in,
                              void* d_out, int out_size)
{
    const float* feature_map = (const float*)d_in[0];
    const float* para_code   = (const float*)d_in[1];
    const float* W1          = (const float*)d_in[2];
    const float* b1          = (const float*)d_in[3];
    const float* Ws          = (const float*)d_in[4];
    const float* bs          = (const float*)d_in[5];
    const float* Wr          = (const float*)d_in[6];
    const float* br          = (const float*)d_in[7];
    const float* Wt          = (const float*)d_in[8];
    const float* bt          = (const float*)d_in[9];
    float*       out         = (float*)d_out;

    int B = in_sizes[1] / PP;   // para_code is (B, 256)
    if (B > MAXB) B = MAXB;

    cudaFuncSetAttribute(adaat_params_kernel,
                         cudaFuncAttributeMaxDynamicSharedMemorySize, SMEM_PAR);

    adaat_params_kernel<<<(B + ROWS - 1) / ROWS, 256, SMEM_PAR>>>(
        para_code, B, W1, b1, Ws, bs, Wr, br, Wt, bt);
    adaat_sample_kernel<<<B, dim3(WW, HH)>>>(feature_map, out);
}